// round 13
// baseline (speedup 1.0000x reference)
#include <cuda_runtime.h>

#define BB 256
#define TT 4096
#define DD 3
#define UU 8
#define SIGD 21
#define CHUNK 16   // TT / 256 threads (kernel A)
#define PF 4       // lstm prefetch depth (steps)

// Scratch: per (b,t,u): {0.5*z_i, z_c, 0.5*z_o, f}  (biases folded)
// Padded so the branchless prefetch ring can read past the end.
__device__ float4 g_G[(size_t)BB * TT * UU + 16 * UU];

__device__ __forceinline__ float ex2f(float x) {
    float y; asm("ex2.approx.f32 %0, %1;" : "=f"(y) : "f"(x)); return y;
}
__device__ __forceinline__ float rcpf(float x) {
    float y; asm("rcp.approx.f32 %0, %1;" : "=f"(y) : "f"(x)); return y;
}
__device__ __forceinline__ float tanha(float x) {        // MUFU.TANH, 1 op
    float y; asm("tanh.approx.f32 %0, %1;" : "=f"(y) : "f"(x)); return y;
}
__device__ __forceinline__ float fsig(float x) {         // accurate sigmoid (kernel A)
    return rcpf(1.0f + ex2f(-1.4426950408889634f * x));
}

// ---------------------------------------------------------------------------
// Kernel A: signature scan + forget gate + input projection (parallel B x T)
// ---------------------------------------------------------------------------
__global__ __launch_bounds__(256) void sig_kernel(
    const float* __restrict__ inp,   // (B,T,3)
    const float* __restrict__ Wi,    // (3,24)
    const float* __restrict__ Wf,    // (21,8)
    const float* __restrict__ bias)  // (32) = [b_i, b_f, b_c, b_o]
{
    __shared__ float sh[2][256][20];
    __shared__ float swf[SIGD * UU];   // 168
    __shared__ float swi[DD * 3 * UU]; // 72
    __shared__ float sb[4 * UU];       // 32

    const int b = blockIdx.x;
    const int j = threadIdx.x;
    if (j < SIGD * UU)   swf[j] = Wf[j];
    if (j < DD * 3 * UU) swi[j] = Wi[j];
    if (j < 4 * UU)      sb[j]  = bias[j];

    const float dt = 1.0f / (float)(TT - 1);
    const int t0 = j * CHUNK;
    const float* ip = inp + ((size_t)b * TT + t0) * DD;

    // ---- pass 1: local chunk signature (diffs t0+1 .. t0+16) ----
    float L1[4] = {0.f, 0.f, 0.f, 0.f};
    float L2[16] = {0.f};
    {
        float p0 = ip[0], p1 = ip[1], p2 = ip[2];
        #pragma unroll
        for (int s = 1; s <= CHUNK; s++) {
            int tg = t0 + s;
            if (tg <= TT - 1) {
                float c0 = ip[s * DD + 0], c1 = ip[s * DD + 1], c2 = ip[s * DD + 2];
                float dx[4] = {dt, c0 - p0, c1 - p1, c2 - p2};
                #pragma unroll
                for (int p = 0; p < 4; p++) {
                    float a = L1[p] + 0.5f * dx[p];
                    #pragma unroll
                    for (int q = 0; q < 4; q++)
                        L2[p * 4 + q] += a * dx[q];
                }
                #pragma unroll
                for (int p = 0; p < 4; p++) L1[p] += dx[p];
                p0 = c0; p1 = c1; p2 = c2;
            }
        }
    }

    // ---- inclusive Hillis-Steele scan of Chen states over 256 chunks ----
    #pragma unroll
    for (int p = 0; p < 4; p++)  sh[0][j][p] = L1[p];
    #pragma unroll
    for (int p = 0; p < 16; p++) sh[0][j][4 + p] = L2[p];
    __syncthreads();

    int cur = 0;
    for (int ofs = 1; ofs < 256; ofs <<= 1) {
        float v[20];
        #pragma unroll
        for (int p = 0; p < 20; p++) v[p] = sh[cur][j][p];
        if (j >= ofs) {
            const float* a = sh[cur][j - ofs];  // earlier aggregate
            float o[20];
            #pragma unroll
            for (int p = 0; p < 4; p++) o[p] = a[p] + v[p];
            #pragma unroll
            for (int p = 0; p < 4; p++)
                #pragma unroll
                for (int q = 0; q < 4; q++)
                    o[4 + p * 4 + q] = a[4 + p * 4 + q] + v[4 + p * 4 + q] + a[p] * v[q];
            #pragma unroll
            for (int p = 0; p < 20; p++) v[p] = o[p];
        }
        #pragma unroll
        for (int p = 0; p < 20; p++) sh[1 - cur][j][p] = v[p];
        __syncthreads();
        cur = 1 - cur;
    }

    // exclusive prefix = signature of path up to time t0
    if (j == 0) {
        #pragma unroll
        for (int p = 0; p < 4; p++)  L1[p] = 0.f;
        #pragma unroll
        for (int p = 0; p < 16; p++) L2[p] = 0.f;
    } else {
        #pragma unroll
        for (int p = 0; p < 4; p++)  L1[p] = sh[cur][j - 1][p];
        #pragma unroll
        for (int p = 0; p < 16; p++) L2[p] = sh[cur][j - 1][4 + p];
    }

    // ---- pass 2: per-timestep signature, forget gate, input projection ----
    float4* Gp = g_G + ((size_t)b * TT) * UU;
    float p0 = ip[0], p1 = ip[1], p2 = ip[2];
    float x0 = p0, x1 = p1, x2 = p2;

    #pragma unroll
    for (int s = 0; s < CHUNK; s++) {
        const int t = t0 + s;
        if (s > 0) {
            float c0 = ip[s * DD + 0], c1 = ip[s * DD + 1], c2 = ip[s * DD + 2];
            float dx[4] = {dt, c0 - p0, c1 - p1, c2 - p2};
            #pragma unroll
            for (int p = 0; p < 4; p++) {
                float a = L1[p] + 0.5f * dx[p];
                #pragma unroll
                for (int q = 0; q < 4; q++)
                    L2[p * 4 + q] += a * dx[q];
            }
            #pragma unroll
            for (int p = 0; p < 4; p++) L1[p] += dx[p];
            p0 = c0; p1 = c1; p2 = c2;
            x0 = c0; x1 = c1; x2 = c2;
        }
        // 4095/t via rcp.approx (rel err ~2^-22, harmless before sigmoid)
        float scale = (t == 0) ? 1.0f : 4095.0f * rcpf((float)t);

        #pragma unroll
        for (int u = 0; u < UU; u++) {
            float acc = swf[u];  // constant term (m=0)
            #pragma unroll
            for (int p = 0; p < 4; p++)  acc += L1[p] * swf[(1 + p) * UU + u];
            #pragma unroll
            for (int p = 0; p < 16; p++) acc += L2[p] * swf[(5 + p) * UU + u];
            float f = fsig(scale * acc + sb[UU + u]);

            float zi = x0 * swi[u]          + x1 * swi[24 + u]          + x2 * swi[48 + u]          + sb[u];
            float zc = x0 * swi[8 + u]      + x1 * swi[24 + 8 + u]      + x2 * swi[48 + 8 + u]      + sb[2 * UU + u];
            float zo = x0 * swi[16 + u]     + x1 * swi[24 + 16 + u]     + x2 * swi[48 + 16 + u]     + sb[3 * UU + u];

            // 0.5 folded for sigmoid-via-tanh in kernel B; z_c stays raw
            Gp[(size_t)t * UU + u] = make_float4(0.5f * zi, zc, 0.5f * zo, f);
        }
    }
}

// ---------------------------------------------------------------------------
// Kernel B: sequential LSTM recurrence. Warp = 4 batches x 8 lanes (lane=unit)
// R6 structure (best known): smem h-exchange with one __syncwarp per step,
// intrinsic loads, compiler-scheduled. New: hx has 4 parities (one per step
// of the unrolled block), so the h history of 4 steps lives in smem; after
// each 4-step block every lane emits ONE coalesced STG.128 covering the
// group's 4x8 output tile (replaces 4 strided STG.32 + address math).
// ---------------------------------------------------------------------------
__global__ __launch_bounds__(32) void lstm_kernel(
    const float* __restrict__ Wr,  // (8,24)
    float* __restrict__ out)       // (B,T,8)
{
    __shared__ float hx[4][4][8];   // [step-parity][group][unit]

    const int lane = threadIdx.x & 31;
    const int g = lane >> 3;
    const int u = lane & 7;
    const int b = blockIdx.x * 4 + g;

    float wi[8], wc[8], wo[8];
    #pragma unroll
    for (int k = 0; k < 8; k++) {
        wi[k] = 0.5f * Wr[k * 24 + u];        // sigmoid path: z/2
        wc[k] =        Wr[k * 24 + 8 + u];    // tanh path: raw z
        wo[k] = 0.5f * Wr[k * 24 + 16 + u];
    }

    const float4* Gp = g_G + ((size_t)b * TT) * UU + u;
    // tile store: lane u covers element range [u*4, u*4+4) of the group's
    // 32-float (4 steps x 8 units) output tile
    float* ot = out + ((size_t)b * TT) * UU + u * 4;

    float hk[8];
    #pragma unroll
    for (int k = 0; k < 8; k++) hk[k] = 0.0f;   // h_{-1} = 0
    float c = 0.0f;

    float4 buf[PF];
    #pragma unroll
    for (int p = 0; p < PF; p++) buf[p] = Gp[(size_t)p * UU];

    for (int t = 0; t < TT; t += PF) {
        #pragma unroll
        for (int k2 = 0; k2 < PF; k2++) {
            float4 v = buf[k2];
            buf[k2] = Gp[(size_t)(t + k2 + PF) * UU];   // branchless (padded)
            float fc = v.w * c;                         // off-chain early

            // balanced tree dots
            float zi, zc, zo;
            {
                float a  = fmaf(hk[1], wi[1], fmaf(hk[0], wi[0], v.x));
                float bb = fmaf(hk[3], wi[3], hk[2] * wi[2]);
                float cc = fmaf(hk[5], wi[5], hk[4] * wi[4]);
                float dd = fmaf(hk[7], wi[7], hk[6] * wi[6]);
                zi = (a + bb) + (cc + dd);
            }
            {
                float a  = fmaf(hk[1], wc[1], fmaf(hk[0], wc[0], v.y));
                float bb = fmaf(hk[3], wc[3], hk[2] * wc[2]);
                float cc = fmaf(hk[5], wc[5], hk[4] * wc[4]);
                float dd = fmaf(hk[7], wc[7], hk[6] * wc[6]);
                zc = (a + bb) + (cc + dd);
            }
            {
                float a  = fmaf(hk[1], wo[1], fmaf(hk[0], wo[0], v.z));
                float bb = fmaf(hk[3], wo[3], hk[2] * wo[2]);
                float cc = fmaf(hk[5], wo[5], hk[4] * wo[4]);
                float dd = fmaf(hk[7], wo[7], hk[6] * wo[6]);
                zo = (a + bb) + (cc + dd);
            }

            float ig = fmaf(0.5f, tanha(zi), 0.5f);   // sigmoid(z_i)
            float cg = tanha(zc);                     // tanh(z_c)
            float og = fmaf(0.5f, tanha(zo), 0.5f);   // sigmoid(z_o)

            c = fmaf(ig, cg, fc);                     // f*c + i*chat
            float h = og * tanha(c);                  // o * tanh(c)

            // --- h exchange via smem (parity = step within block) ---
            hx[k2][g][u] = h;
            __syncwarp();
            float4 lo  = *reinterpret_cast<const float4*>(&hx[k2][g][0]);
            float4 hi4 = *reinterpret_cast<const float4*>(&hx[k2][g][4]);
            hk[0] = lo.x;  hk[1] = lo.y;  hk[2] = lo.z;  hk[3] = lo.w;
            hk[4] = hi4.x; hk[5] = hi4.y; hk[6] = hi4.z; hk[7] = hi4.w;
        }

        // --- coalesced tile store: 4 steps x 8 units = 32 floats per group,
        // element e = u*4+j  ->  step t+(u>>1), unit (u&1)*4+j, i.e. lane u
        // reads float4 from hx[u>>1][g][(u&1)*4]  (h history of this block)
        {
            float4 tile = *reinterpret_cast<const float4*>(&hx[u >> 1][g][(u & 1) * 4]);
            *reinterpret_cast<float4*>(&ot[(size_t)t * UU]) = tile;
            __syncwarp();   // protect hx from next block's overwrite
        }
    }
}

// ---------------------------------------------------------------------------
extern "C" void kernel_launch(void* const* d_in, const int* in_sizes, int n_in,
                              void* d_out, int out_size) {
    const float* inputs = (const float*)d_in[0];  // (256,4096,3)
    const float* Wi     = (const float*)d_in[1];  // (3,24)
    const float* Wr     = (const float*)d_in[2];  // (8,24)
    const float* Wf     = (const float*)d_in[3];  // (21,8)
    const float* bias   = (const float*)d_in[4];  // (32)
    float* out = (float*)d_out;                   // (256,4096,8) f32

    sig_kernel<<<BB, 256>>>(inputs, Wi, Wf, bias);
    lstm_kernel<<<BB / 4, 32>>>(Wr, out);
}

// round 14
// speedup vs baseline: 1.3727x; 1.3727x over previous
#include <cuda_runtime.h>

#define BB 256
#define TT 4096
#define DD 3
#define UU 8
#define SIGD 21
#define CHUNK 16   // TT / 256 threads (kernel A)
#define PF 8       // lstm prefetch depth (steps) — PF=8 is load-bearing (R10/12/13)

// Scratch: per (b,t,u): {0.5*z_i, z_c, 0.5*z_o, f}  (biases folded)
// Padded so the branchless prefetch ring can read past the end.
__device__ float4 g_G[(size_t)BB * TT * UU + 16 * UU];

__device__ __forceinline__ float ex2f(float x) {
    float y; asm("ex2.approx.f32 %0, %1;" : "=f"(y) : "f"(x)); return y;
}
__device__ __forceinline__ float rcpf(float x) {
    float y; asm("rcp.approx.f32 %0, %1;" : "=f"(y) : "f"(x)); return y;
}
__device__ __forceinline__ float tanha(float x) {        // MUFU.TANH, 1 op
    float y; asm("tanh.approx.f32 %0, %1;" : "=f"(y) : "f"(x)); return y;
}
__device__ __forceinline__ float fsig(float x) {         // accurate sigmoid (kernel A)
    return rcpf(1.0f + ex2f(-1.4426950408889634f * x));
}

// ---------------------------------------------------------------------------
// Kernel A: signature scan + forget gate + input projection (parallel B x T)
// ---------------------------------------------------------------------------
__global__ __launch_bounds__(256) void sig_kernel(
    const float* __restrict__ inp,   // (B,T,3)
    const float* __restrict__ Wi,    // (3,24)
    const float* __restrict__ Wf,    // (21,8)
    const float* __restrict__ bias)  // (32) = [b_i, b_f, b_c, b_o]
{
    __shared__ float sh[2][256][20];
    __shared__ float swf[SIGD * UU];   // 168
    __shared__ float swi[DD * 3 * UU]; // 72
    __shared__ float sb[4 * UU];       // 32

    const int b = blockIdx.x;
    const int j = threadIdx.x;
    if (j < SIGD * UU)   swf[j] = Wf[j];
    if (j < DD * 3 * UU) swi[j] = Wi[j];
    if (j < 4 * UU)      sb[j]  = bias[j];

    const float dt = 1.0f / (float)(TT - 1);
    const int t0 = j * CHUNK;
    const float* ip = inp + ((size_t)b * TT + t0) * DD;

    // ---- pass 1: local chunk signature (diffs t0+1 .. t0+16) ----
    float L1[4] = {0.f, 0.f, 0.f, 0.f};
    float L2[16] = {0.f};
    {
        float p0 = ip[0], p1 = ip[1], p2 = ip[2];
        #pragma unroll
        for (int s = 1; s <= CHUNK; s++) {
            int tg = t0 + s;
            if (tg <= TT - 1) {
                float c0 = ip[s * DD + 0], c1 = ip[s * DD + 1], c2 = ip[s * DD + 2];
                float dx[4] = {dt, c0 - p0, c1 - p1, c2 - p2};
                #pragma unroll
                for (int p = 0; p < 4; p++) {
                    float a = L1[p] + 0.5f * dx[p];
                    #pragma unroll
                    for (int q = 0; q < 4; q++)
                        L2[p * 4 + q] += a * dx[q];
                }
                #pragma unroll
                for (int p = 0; p < 4; p++) L1[p] += dx[p];
                p0 = c0; p1 = c1; p2 = c2;
            }
        }
    }

    // ---- inclusive Hillis-Steele scan of Chen states over 256 chunks ----
    #pragma unroll
    for (int p = 0; p < 4; p++)  sh[0][j][p] = L1[p];
    #pragma unroll
    for (int p = 0; p < 16; p++) sh[0][j][4 + p] = L2[p];
    __syncthreads();

    int cur = 0;
    for (int ofs = 1; ofs < 256; ofs <<= 1) {
        float v[20];
        #pragma unroll
        for (int p = 0; p < 20; p++) v[p] = sh[cur][j][p];
        if (j >= ofs) {
            const float* a = sh[cur][j - ofs];  // earlier aggregate
            float o[20];
            #pragma unroll
            for (int p = 0; p < 4; p++) o[p] = a[p] + v[p];
            #pragma unroll
            for (int p = 0; p < 4; p++)
                #pragma unroll
                for (int q = 0; q < 4; q++)
                    o[4 + p * 4 + q] = a[4 + p * 4 + q] + v[4 + p * 4 + q] + a[p] * v[q];
            #pragma unroll
            for (int p = 0; p < 20; p++) v[p] = o[p];
        }
        #pragma unroll
        for (int p = 0; p < 20; p++) sh[1 - cur][j][p] = v[p];
        __syncthreads();
        cur = 1 - cur;
    }

    // exclusive prefix = signature of path up to time t0
    if (j == 0) {
        #pragma unroll
        for (int p = 0; p < 4; p++)  L1[p] = 0.f;
        #pragma unroll
        for (int p = 0; p < 16; p++) L2[p] = 0.f;
    } else {
        #pragma unroll
        for (int p = 0; p < 4; p++)  L1[p] = sh[cur][j - 1][p];
        #pragma unroll
        for (int p = 0; p < 16; p++) L2[p] = sh[cur][j - 1][4 + p];
    }

    // ---- pass 2: per-timestep signature, forget gate, input projection ----
    float4* Gp = g_G + ((size_t)b * TT) * UU;
    float p0 = ip[0], p1 = ip[1], p2 = ip[2];
    float x0 = p0, x1 = p1, x2 = p2;

    #pragma unroll
    for (int s = 0; s < CHUNK; s++) {
        const int t = t0 + s;
        if (s > 0) {
            float c0 = ip[s * DD + 0], c1 = ip[s * DD + 1], c2 = ip[s * DD + 2];
            float dx[4] = {dt, c0 - p0, c1 - p1, c2 - p2};
            #pragma unroll
            for (int p = 0; p < 4; p++) {
                float a = L1[p] + 0.5f * dx[p];
                #pragma unroll
                for (int q = 0; q < 4; q++)
                    L2[p * 4 + q] += a * dx[q];
            }
            #pragma unroll
            for (int p = 0; p < 4; p++) L1[p] += dx[p];
            p0 = c0; p1 = c1; p2 = c2;
            x0 = c0; x1 = c1; x2 = c2;
        }
        // 4095/t via rcp.approx (rel err ~2^-22, harmless before sigmoid)
        float scale = (t == 0) ? 1.0f : 4095.0f * rcpf((float)t);

        #pragma unroll
        for (int u = 0; u < UU; u++) {
            float acc = swf[u];  // constant term (m=0)
            #pragma unroll
            for (int p = 0; p < 4; p++)  acc += L1[p] * swf[(1 + p) * UU + u];
            #pragma unroll
            for (int p = 0; p < 16; p++) acc += L2[p] * swf[(5 + p) * UU + u];
            float f = fsig(scale * acc + sb[UU + u]);

            float zi = x0 * swi[u]          + x1 * swi[24 + u]          + x2 * swi[48 + u]          + sb[u];
            float zc = x0 * swi[8 + u]      + x1 * swi[24 + 8 + u]      + x2 * swi[48 + 8 + u]      + sb[2 * UU + u];
            float zo = x0 * swi[16 + u]     + x1 * swi[24 + 16 + u]     + x2 * swi[48 + 16 + u]     + sb[3 * UU + u];

            // 0.5 folded for sigmoid-via-tanh in kernel B; z_c stays raw
            Gp[(size_t)t * UU + u] = make_float4(0.5f * zi, zc, 0.5f * zo, f);
        }
    }
}

// ---------------------------------------------------------------------------
// Kernel B: sequential LSTM recurrence. Warp = 4 batches x 8 lanes (lane=unit)
// EXACT R6 structure (best known: PF=8, intrinsic smem exchange, plain
// indexed loads/stores, compiler-scheduled) with ONE change: the per-step
// __syncwarp() is replaced by a zero-instruction compiler fence. The warp is
// fully convergent (no divergent branches), so STS->LDS lockstep ordering is
// HW-guaranteed; the fence only preserves compiler ordering, deleting the
// WARPSYNC (~23 cyc/step).
// ---------------------------------------------------------------------------
__global__ __launch_bounds__(32) void lstm_kernel(
    const float* __restrict__ Wr,  // (8,24)
    float* __restrict__ out)       // (B,T,8)
{
    __shared__ float hx[2][4][8];   // [parity][group][unit]

    const int lane = threadIdx.x;
    const int g = lane >> 3;
    const int u = lane & 7;
    const int b = blockIdx.x * 4 + g;

    float wi[8], wc[8], wo[8];
    #pragma unroll
    for (int k = 0; k < 8; k++) {
        wi[k] = 0.5f * Wr[k * 24 + u];        // sigmoid path: z/2
        wc[k] =        Wr[k * 24 + 8 + u];    // tanh path: raw z
        wo[k] = 0.5f * Wr[k * 24 + 16 + u];
    }

    const float4* Gp = g_G + ((size_t)b * TT) * UU + u;
    float* op_ = out + ((size_t)b * TT) * UU + u;

    float hk[8];
    #pragma unroll
    for (int k = 0; k < 8; k++) hk[k] = 0.0f;   // h_{-1} = 0
    float c = 0.0f;

    float4 buf[PF];
    #pragma unroll
    for (int p = 0; p < PF; p++) buf[p] = Gp[(size_t)p * UU];

    for (int t = 0; t < TT; t += PF) {
        #pragma unroll
        for (int k2 = 0; k2 < PF; k2++) {
            float4 v = buf[k2];
            buf[k2] = Gp[(size_t)(t + k2 + PF) * UU];   // branchless (padded scratch)
            float fc = v.w * c;                         // same arithmetic as R6

            // balanced tree dots
            float zi, zc, zo;
            {
                float a  = fmaf(hk[1], wi[1], fmaf(hk[0], wi[0], v.x));
                float bb = fmaf(hk[3], wi[3], hk[2] * wi[2]);
                float cc = fmaf(hk[5], wi[5], hk[4] * wi[4]);
                float dd = fmaf(hk[7], wi[7], hk[6] * wi[6]);
                zi = (a + bb) + (cc + dd);
            }
            {
                float a  = fmaf(hk[1], wc[1], fmaf(hk[0], wc[0], v.y));
                float bb = fmaf(hk[3], wc[3], hk[2] * wc[2]);
                float cc = fmaf(hk[5], wc[5], hk[4] * wc[4]);
                float dd = fmaf(hk[7], wc[7], hk[6] * wc[6]);
                zc = (a + bb) + (cc + dd);
            }
            {
                float a  = fmaf(hk[1], wo[1], fmaf(hk[0], wo[0], v.z));
                float bb = fmaf(hk[3], wo[3], hk[2] * wo[2]);
                float cc = fmaf(hk[5], wo[5], hk[4] * wo[4]);
                float dd = fmaf(hk[7], wo[7], hk[6] * wo[6]);
                zo = (a + bb) + (cc + dd);
            }

            float ig = fmaf(0.5f, tanha(zi), 0.5f);   // sigmoid(z_i)
            float cg = tanha(zc);                     // tanh(z_c)
            float og = fmaf(0.5f, tanha(zo), 0.5f);   // sigmoid(z_o)

            c = fmaf(ig, cg, fc);                     // f*c + i*chat
            float h = og * tanha(c);                  // o * tanh(c)

            op_[(size_t)(t + k2) * UU] = h;

            // --- h broadcast via smem: warp-synchronous (convergent warp),
            // compiler fence only — no WARPSYNC instruction ---
            hx[k2 & 1][g][u] = h;
            asm volatile("" ::: "memory");
            float4 lo  = *reinterpret_cast<const float4*>(&hx[k2 & 1][g][0]);
            float4 hi4 = *reinterpret_cast<const float4*>(&hx[k2 & 1][g][4]);
            hk[0] = lo.x;  hk[1] = lo.y;  hk[2] = lo.z;  hk[3] = lo.w;
            hk[4] = hi4.x; hk[5] = hi4.y; hk[6] = hi4.z; hk[7] = hi4.w;
        }
    }
}

// ---------------------------------------------------------------------------
extern "C" void kernel_launch(void* const* d_in, const int* in_sizes, int n_in,
                              void* d_out, int out_size) {
    const float* inputs = (const float*)d_in[0];  // (256,4096,3)
    const float* Wi     = (const float*)d_in[1];  // (3,24)
    const float* Wr     = (const float*)d_in[2];  // (8,24)
    const float* Wf     = (const float*)d_in[3];  // (21,8)
    const float* bias   = (const float*)d_in[4];  // (32)
    float* out = (float*)d_out;                   // (256,4096,8) f32

    sig_kernel<<<BB, 256>>>(inputs, Wi, Wf, bias);
    lstm_kernel<<<BB / 4, 32>>>(Wr, out);
}